// round 5
// baseline (speedup 1.0000x reference)
#include <cuda_runtime.h>
#include <cuda_bf16.h>
#include <math.h>

// ----------------------------------------------------------------------------
// Attention_13314398617962   (t=512, b=64, s=1024, hu=1024)
//   scores[t,b] = MLP(concat(si[b], h[t,b]))   (2048 -> 10 -> 5 -> 1, BN+relu)
//   a = softmax(scores.flatten())              (over all 32768)
//   ci[b,:] = sum_tau a[tau] * h[tau_t, tau_b, :]   (tau < 512)
// ----------------------------------------------------------------------------

#define T_DIM 512
#define B_DIM 64
#define HU 1024
#define NROWS (T_DIM * B_DIM)   // 32768
#define RPB 16                  // rows per block in score kernel
#define NBLK (NROWS / RPB)      // 2048
#define RSTRIDE 644             // padded floats per row-slot in red[]

__device__ float g_pre0[B_DIM * 10];   // si @ W0[:1024] per b (raw dot)
__device__ float g_ep[30];             // s0[10] t0[10] s1[5] t1[5]
__device__ float g_scores[T_DIM];      // raw scores for rows < 512
__device__ float g_w[T_DIM];           // softmax weights
__device__ float g_bmax[NBLK];
__device__ float g_bsum[NBLK];

// ---------------------------------------------------------------------------
__device__ __forceinline__ void ffma2(unsigned long long& d,
                                      unsigned long long a,
                                      unsigned long long b)
{
    asm("fma.rn.f32x2 %0, %1, %2, %0;" : "+l"(d) : "l"(a), "l"(b));
}
__device__ __forceinline__ void fmul2(unsigned long long& d,
                                      unsigned long long a,
                                      unsigned long long b)
{
    asm("mul.rn.f32x2 %0, %1, %2;" : "=l"(d) : "l"(a), "l"(b));
}
__device__ __forceinline__ unsigned long long pack2(float x)
{
    unsigned long long r;
    asm("mov.b64 %0, {%1, %1};" : "=l"(r) : "f"(x));
    return r;
}
__device__ __forceinline__ void unpack2(unsigned long long v, float& lo, float& hi)
{
    asm("mov.b64 {%0, %1}, %2;" : "=f"(lo), "=f"(hi) : "l"(v));
}

// ---------------------------------------------------------------------------
// K0: per-b si contribution (coalesced W0 reads) + folded BN constants.
// ---------------------------------------------------------------------------
__global__ __launch_bounds__(256)
void prep_kernel(const float* __restrict__ si,
                 const float* __restrict__ W0,
                 const float* __restrict__ b0,
                 const float* __restrict__ g0,
                 const float* __restrict__ be0,
                 const float* __restrict__ m0,
                 const float* __restrict__ v0,
                 const float* __restrict__ b1,
                 const float* __restrict__ g1,
                 const float* __restrict__ be1,
                 const float* __restrict__ m1,
                 const float* __restrict__ v1)
{
    __shared__ float red[64][10];

    int b = blockIdx.x;
    int tid = threadIdx.x;
    int lane = tid & 31;
    int warp = tid >> 5;

    float wv[40];
    {
        const float4* wp = reinterpret_cast<const float4*>(W0 + 4 * tid * 10);
#pragma unroll
        for (int i = 0; i < 10; ++i)
            reinterpret_cast<float4*>(wv)[i] = wp[i];
    }
    float4 sv = reinterpret_cast<const float4*>(si + b * 1024)[tid];

    float pj[10];
#pragma unroll
    for (int j = 0; j < 10; ++j) {
        float a = sv.x * wv[j];
        a = fmaf(sv.y, wv[10 + j], a);
        a = fmaf(sv.z, wv[20 + j], a);
        a = fmaf(sv.w, wv[30 + j], a);
        pj[j] = a;
    }
#pragma unroll
    for (int j = 0; j < 10; ++j) {
        pj[j] += __shfl_xor_sync(0xffffffffu, pj[j], 16);
        pj[j] += __shfl_xor_sync(0xffffffffu, pj[j], 8);
    }
    if (lane < 8) {
#pragma unroll
        for (int j = 0; j < 10; ++j) red[warp * 8 + lane][j] = pj[j];
    }
    __syncthreads();

    if (tid < 10) {
        float s = 0.f;
#pragma unroll
        for (int q = 0; q < 64; ++q) s += red[q][tid];
        g_pre0[b * 10 + tid] = s;
    }

    if (b == 0) {
        if (tid >= 32 && tid < 42) {
            int i = tid - 32;
            float s = g0[i] * (1.0f / sqrtf(v0[i] + 1e-5f));
            g_ep[i] = s;
            g_ep[10 + i] = (b0[i] - m0[i]) * s + be0[i];
        } else if (tid >= 64 && tid < 69) {
            int i = tid - 64;
            float s = g1[i] * (1.0f / sqrtf(v1[i] + 1e-5f));
            g_ep[20 + i] = s;
            g_ep[25 + i] = (b1[i] - m1[i]) * s + be1[i];
        }
    }
}

// ---------------------------------------------------------------------------
// K1: scores + per-block online softmax stats. 16 rows/block, 2048 blocks.
// 256 threads cover ONE row per iteration: thread owns k = 4*tid..4*tid+3
// (40 weight floats as 20 packed f32x2). 8-deep float4 prefetch ring
// (16 KB in flight per SM at 2 blocks/SM -> DRAM latency covered).
// Per row: 1 LDG.128, 4 packs, 20 FFMA2, 20 SHFL, 5 STS.64 (lane<8).
// No barrier in the loop (distinct smem slot per row; padded stride 644
// makes the end-reduce bank-conflict-free).
// ---------------------------------------------------------------------------
__global__ __launch_bounds__(256, 2)
void score_kernel(const float* __restrict__ h,
                  const float* __restrict__ W0,
                  const float* __restrict__ W1,
                  const float* __restrict__ W2,
                  const float* __restrict__ b2)
{
    __shared__ float red[RPB * RSTRIDE];      // [row][part*10 + j], padded (41.2 KB)
    __shared__ float pre0s[RPB * 10];
    __shared__ float dsum[RPB * 10];
    __shared__ float epi[86];                 // s0 t0 s1 t1 W1[50] W2[5] b2

    int tid  = threadIdx.x;
    int lane = tid & 31;
    int warp = tid >> 5;
    int rowbase = blockIdx.x * RPB;
    int bbase   = rowbase & 63;

    if (tid < 30)                  epi[tid] = g_ep[tid];
    if (tid >= 32 && tid < 82)     epi[30 + tid - 32] = W1[tid - 32];
    if (tid >= 96 && tid < 101)    epi[80 + tid - 96] = W2[tid - 96];
    if (tid == 101)                epi[85] = b2[0];
    if (tid < RPB * 10)            pre0s[tid] = g_pre0[bbase * 10 + tid];

    // 40 weight floats as 20 packed f32x2: u[kk*5+p]
    union { float4 v[10]; unsigned long long u[20]; } wr;
    {
        const float4* wp = reinterpret_cast<const float4*>(W0 + (1024 + 4 * tid) * 10);
#pragma unroll
        for (int i = 0; i < 10; ++i) wr.v[i] = wp[i];
    }

    const float* hb = h + (size_t)rowbase * 1024 + 4 * tid;
    float4 P[8];
#pragma unroll
    for (int i = 0; i < 8; ++i)
        P[i] = *reinterpret_cast<const float4*>(hb + (size_t)i * 1024);

    __syncthreads();   // smem staging visible

    float* myred = red + (warp * 8 + (lane & 7)) * 10;

#pragma unroll 8
    for (int it = 0; it < RPB; ++it) {
        float4 cv = P[it & 7];
        if (it < RPB - 8)
            P[it & 7] = *reinterpret_cast<const float4*>(hb + (size_t)(it + 8) * 1024);

        unsigned long long acc[5];
        unsigned long long hh;
        hh = pack2(cv.x);
#pragma unroll
        for (int p = 0; p < 5; ++p) fmul2(acc[p], hh, wr.u[p]);
        hh = pack2(cv.y);
#pragma unroll
        for (int p = 0; p < 5; ++p) ffma2(acc[p], hh, wr.u[5 + p]);
        hh = pack2(cv.z);
#pragma unroll
        for (int p = 0; p < 5; ++p) ffma2(acc[p], hh, wr.u[10 + p]);
        hh = pack2(cv.w);
#pragma unroll
        for (int p = 0; p < 5; ++p) ffma2(acc[p], hh, wr.u[15 + p]);

        float pj[10];
#pragma unroll
        for (int p = 0; p < 5; ++p) unpack2(acc[p], pj[2 * p], pj[2 * p + 1]);

#pragma unroll
        for (int j = 0; j < 10; ++j) {
            pj[j] += __shfl_xor_sync(0xffffffffu, pj[j], 16);
            pj[j] += __shfl_xor_sync(0xffffffffu, pj[j], 8);
        }
        if (lane < 8) {
            float2* rb = reinterpret_cast<float2*>(myred + it * RSTRIDE);
#pragma unroll
            for (int p = 0; p < 5; ++p) rb[p] = make_float2(pj[2 * p], pj[2 * p + 1]);
        }
    }
    __syncthreads();

    // block reduce: 160 (row,j) sums, each over 64 partials (stride 10 floats,
    // row stride RSTRIDE=644 -> conflict-free across the warp)
    if (tid < RPB * 10) {
        int rl = tid / 10;
        int j  = tid - rl * 10;
        const float* base = red + rl * RSTRIDE + j;
        float s0 = 0.f, s1 = 0.f, s2 = 0.f, s3 = 0.f;
#pragma unroll
        for (int q = 0; q < 16; ++q) {
            s0 += base[(4 * q) * 10];
            s1 += base[(4 * q + 1) * 10];
            s2 += base[(4 * q + 2) * 10];
            s3 += base[(4 * q + 3) * 10];
        }
        dsum[tid] = (s0 + s1) + (s2 + s3);
    }
    __syncthreads();

    // fused MLP epilogue (16 rows) + warp-0 online softmax stats
    if (tid < 32) {
        float sc = -1e30f;
        if (tid < RPB) {
            int row = rowbase + tid;
            float x0[10];
#pragma unroll
            for (int j = 0; j < 10; ++j) {
                float d = dsum[tid * 10 + j] + pre0s[tid * 10 + j];
                x0[j] = fmaxf(fmaf(d, epi[j], epi[10 + j]), 0.f);
            }
            sc = epi[85];
#pragma unroll
            for (int i = 0; i < 5; ++i) {
                float z = 0.f;
#pragma unroll
                for (int j = 0; j < 10; ++j)
                    z = fmaf(x0[j], epi[30 + j * 5 + i], z);
                float x1 = fmaxf(fmaf(z, epi[20 + i], epi[25 + i]), 0.f);
                sc = fmaf(x1, epi[80 + i], sc);
            }
            if (row < T_DIM) g_scores[row] = sc;
        }
        float m = sc;
#pragma unroll
        for (int o = 16; o > 0; o >>= 1)
            m = fmaxf(m, __shfl_xor_sync(0xffffffffu, m, o));
        float e = (tid < RPB) ? expf(sc - m) : 0.f;
#pragma unroll
        for (int o = 16; o > 0; o >>= 1)
            e += __shfl_xor_sync(0xffffffffu, e, o);
        if (tid == 0) {
            g_bmax[blockIdx.x] = m;
            g_bsum[blockIdx.x] = e;
        }
    }
}

// ---------------------------------------------------------------------------
// K2: combine 2048 (max, expsum) pairs -> M, S; write 512 weights.
// ---------------------------------------------------------------------------
__global__ void combine_kernel()
{
    __shared__ float sm[512];
    __shared__ float MS[2];
    int tid = threadIdx.x;

    float lm = -1e30f;
    float bm[4];
#pragma unroll
    for (int i = 0; i < 4; ++i) {
        bm[i] = g_bmax[tid * 4 + i];
        lm = fmaxf(lm, bm[i]);
    }
    sm[tid] = lm;
    __syncthreads();
    for (int s = 256; s > 0; s >>= 1) {
        if (tid < s) sm[tid] = fmaxf(sm[tid], sm[tid + s]);
        __syncthreads();
    }
    if (tid == 0) MS[0] = sm[0];
    __syncthreads();
    float M = MS[0];

    float ls = 0.f;
#pragma unroll
    for (int i = 0; i < 4; ++i)
        ls += g_bsum[tid * 4 + i] * expf(bm[i] - M);
    sm[tid] = ls;
    __syncthreads();
    for (int s = 256; s > 0; s >>= 1) {
        if (tid < s) sm[tid] += sm[tid + s];
        __syncthreads();
    }
    if (tid == 0) MS[1] = 1.0f / sm[0];
    __syncthreads();

    g_w[tid] = expf(g_scores[tid] - M) * MS[1];
}

// ---------------------------------------------------------------------------
// K3: ci[b,:] = sum_tau w[tau] * h[tau,b,:]
// grid (8 chunks of 128 cols, 64 b) x 512 threads. Each warp runs TWO
// independent t-streams (t = i*32+w and i*32+16+w) -> 2x memory-level
// parallelism per thread.
// ---------------------------------------------------------------------------
__global__ __launch_bounds__(512)
void wsum_kernel(const float* __restrict__ h, float* __restrict__ out)
{
    __shared__ float ws[T_DIM];
    __shared__ float part[16][128];

    int tid  = threadIdx.x;
    int w    = tid >> 5;
    int lane = tid & 31;
    int c = blockIdx.x;           // 128-col chunk
    int b = blockIdx.y;

    if (tid < 128)
        reinterpret_cast<float4*>(ws)[tid] = reinterpret_cast<const float4*>(g_w)[tid];
    __syncthreads();

    const float* hp = h + (size_t)b * 1024 + c * 128 + 4 * lane;
    float4 acc0 = make_float4(0.f, 0.f, 0.f, 0.f);
    float4 acc1 = make_float4(0.f, 0.f, 0.f, 0.f);
#pragma unroll 4
    for (int i = 0; i < T_DIM / 32; ++i) {
        int t0 = i * 32 + w;
        int t1 = t0 + 16;
        float4 hv0 = *reinterpret_cast<const float4*>(hp + (size_t)t0 * (B_DIM * HU));
        float4 hv1 = *reinterpret_cast<const float4*>(hp + (size_t)t1 * (B_DIM * HU));
        float w0 = ws[t0];
        float w1 = ws[t1];
        acc0.x = fmaf(w0, hv0.x, acc0.x);
        acc0.y = fmaf(w0, hv0.y, acc0.y);
        acc0.z = fmaf(w0, hv0.z, acc0.z);
        acc0.w = fmaf(w0, hv0.w, acc0.w);
        acc1.x = fmaf(w1, hv1.x, acc1.x);
        acc1.y = fmaf(w1, hv1.y, acc1.y);
        acc1.z = fmaf(w1, hv1.z, acc1.z);
        acc1.w = fmaf(w1, hv1.w, acc1.w);
    }
    acc0.x += acc1.x; acc0.y += acc1.y; acc0.z += acc1.z; acc0.w += acc1.w;
    *reinterpret_cast<float4*>(&part[w][4 * lane]) = acc0;
    __syncthreads();

    if (tid < 128) {
        float s0 = part[0][tid], s1 = part[1][tid];
        float s2 = part[2][tid], s3 = part[3][tid];
#pragma unroll
        for (int q = 4; q < 16; q += 4) {
            s0 += part[q][tid];
            s1 += part[q + 1][tid];
            s2 += part[q + 2][tid];
            s3 += part[q + 3][tid];
        }
        out[b * 1024 + c * 128 + tid] = (s0 + s1) + (s2 + s3);
    }
}

// ---------------------------------------------------------------------------
extern "C" void kernel_launch(void* const* d_in, const int* in_sizes, int n_in,
                              void* d_out, int out_size)
{
    const float* si  = (const float*)d_in[0];
    const float* h   = (const float*)d_in[1];
    const float* W0  = (const float*)d_in[2];
    const float* b0  = (const float*)d_in[3];
    const float* g0  = (const float*)d_in[4];
    const float* be0 = (const float*)d_in[5];
    const float* m0  = (const float*)d_in[6];
    const float* v0  = (const float*)d_in[7];
    const float* W1  = (const float*)d_in[8];
    const float* b1  = (const float*)d_in[9];
    const float* g1  = (const float*)d_in[10];
    const float* be1 = (const float*)d_in[11];
    const float* m1  = (const float*)d_in[12];
    const float* v1  = (const float*)d_in[13];
    const float* W2  = (const float*)d_in[14];
    const float* b2  = (const float*)d_in[15];
    float* out = (float*)d_out;

    prep_kernel<<<B_DIM, 256>>>(si, W0, b0, g0, be0, m0, v0, b1, g1, be1, m1, v1);
    score_kernel<<<NBLK, 256>>>(h, W0, W1, W2, b2);
    combine_kernel<<<1, 512>>>();
    wsum_kernel<<<dim3(8, B_DIM), 512>>>(h, out);
}

// round 6
// speedup vs baseline: 1.3342x; 1.3342x over previous
#include <cuda_runtime.h>
#include <cuda_bf16.h>
#include <math.h>

// ----------------------------------------------------------------------------
// Attention_13314398617962   (t=512, b=64, s=1024, hu=1024)
//   scores[t,b] = MLP(concat(si[b], h[t,b]))   (2048 -> 10 -> 5 -> 1, BN+relu)
//   a = softmax(scores.flatten())              (over all 32768)
//   ci[b,:] = sum_tau a[tau] * h[tau_t, tau_b, :]   (tau < 512)
// ----------------------------------------------------------------------------

#define T_DIM 512
#define B_DIM 64
#define HU 1024
#define NROWS (T_DIM * B_DIM)   // 32768
#define RPB 16                  // rows per block in score kernel
#define NBLK (NROWS / RPB)      // 2048
#define RSTRIDE 644             // padded floats per row-slot in red[]

__device__ float g_pre0[B_DIM * 10];   // si @ W0[:1024] per b (raw dot)
__device__ float g_ep[30];             // s0[10] t0[10] s1[5] t1[5]
__device__ float g_scores[T_DIM];      // raw scores for rows < 512
__device__ float g_w[T_DIM];           // softmax weights
__device__ float g_bmax[NBLK];
__device__ float g_bsum[NBLK];

// ---------------------------------------------------------------------------
__device__ __forceinline__ void ffma2(unsigned long long& d,
                                      unsigned long long a,
                                      unsigned long long b)
{
    asm("fma.rn.f32x2 %0, %1, %2, %0;" : "+l"(d) : "l"(a), "l"(b));
}
__device__ __forceinline__ void fmul2(unsigned long long& d,
                                      unsigned long long a,
                                      unsigned long long b)
{
    asm("mul.rn.f32x2 %0, %1, %2;" : "=l"(d) : "l"(a), "l"(b));
}
__device__ __forceinline__ unsigned long long pack2(float x)
{
    unsigned long long r;
    asm("mov.b64 %0, {%1, %1};" : "=l"(r) : "f"(x));
    return r;
}
__device__ __forceinline__ void unpack2(unsigned long long v, float& lo, float& hi)
{
    asm("mov.b64 {%0, %1}, %2;" : "=f"(lo), "=f"(hi) : "l"(v));
}

// ---------------------------------------------------------------------------
// K0: per-b si contribution (coalesced W0 reads) + folded BN constants.
// ---------------------------------------------------------------------------
__global__ __launch_bounds__(256)
void prep_kernel(const float* __restrict__ si,
                 const float* __restrict__ W0,
                 const float* __restrict__ b0,
                 const float* __restrict__ g0,
                 const float* __restrict__ be0,
                 const float* __restrict__ m0,
                 const float* __restrict__ v0,
                 const float* __restrict__ b1,
                 const float* __restrict__ g1,
                 const float* __restrict__ be1,
                 const float* __restrict__ m1,
                 const float* __restrict__ v1)
{
    __shared__ float red[64][10];

    int b = blockIdx.x;
    int tid = threadIdx.x;
    int lane = tid & 31;
    int warp = tid >> 5;

    float wv[40];
    {
        const float4* wp = reinterpret_cast<const float4*>(W0 + 4 * tid * 10);
#pragma unroll
        for (int i = 0; i < 10; ++i)
            reinterpret_cast<float4*>(wv)[i] = wp[i];
    }
    float4 sv = reinterpret_cast<const float4*>(si + b * 1024)[tid];

    float pj[10];
#pragma unroll
    for (int j = 0; j < 10; ++j) {
        float a = sv.x * wv[j];
        a = fmaf(sv.y, wv[10 + j], a);
        a = fmaf(sv.z, wv[20 + j], a);
        a = fmaf(sv.w, wv[30 + j], a);
        pj[j] = a;
    }
#pragma unroll
    for (int j = 0; j < 10; ++j) {
        pj[j] += __shfl_xor_sync(0xffffffffu, pj[j], 16);
        pj[j] += __shfl_xor_sync(0xffffffffu, pj[j], 8);
    }
    if (lane < 8) {
#pragma unroll
        for (int j = 0; j < 10; ++j) red[warp * 8 + lane][j] = pj[j];
    }
    __syncthreads();

    if (tid < 10) {
        float s = 0.f;
#pragma unroll
        for (int q = 0; q < 64; ++q) s += red[q][tid];
        g_pre0[b * 10 + tid] = s;
    }

    if (b == 0) {
        if (tid >= 32 && tid < 42) {
            int i = tid - 32;
            float s = g0[i] * (1.0f / sqrtf(v0[i] + 1e-5f));
            g_ep[i] = s;
            g_ep[10 + i] = (b0[i] - m0[i]) * s + be0[i];
        } else if (tid >= 64 && tid < 69) {
            int i = tid - 64;
            float s = g1[i] * (1.0f / sqrtf(v1[i] + 1e-5f));
            g_ep[20 + i] = s;
            g_ep[25 + i] = (b1[i] - m1[i]) * s + be1[i];
        }
    }
}

// ---------------------------------------------------------------------------
// K1: scores + per-block online softmax stats. 16 rows/block, 2048 blocks.
// 256 threads cover ONE row per iteration: thread owns k = 4*tid..4*tid+3
// (40 weight floats as 20 packed f32x2). 4-deep float4 prefetch ring
// (~98 regs -> NO spills at the 128-reg cap; prefetch distance 4 iters
// ~ 640 cyc > DRAM latency). Per row: 1 LDG.128, 4 packs, 20 FFMA2,
// 20 SHFL, 5 STS.64 (lane<8). No barrier in the loop.
// ---------------------------------------------------------------------------
__global__ __launch_bounds__(256, 2)
void score_kernel(const float* __restrict__ h,
                  const float* __restrict__ W0,
                  const float* __restrict__ W1,
                  const float* __restrict__ W2,
                  const float* __restrict__ b2)
{
    __shared__ float red[RPB * RSTRIDE];      // [row][part*10 + j], padded (41.2 KB)
    __shared__ float pre0s[RPB * 10];
    __shared__ float dsum[RPB * 10];
    __shared__ float epi[86];                 // s0 t0 s1 t1 W1[50] W2[5] b2

    int tid  = threadIdx.x;
    int lane = tid & 31;
    int warp = tid >> 5;
    int rowbase = blockIdx.x * RPB;
    int bbase   = rowbase & 63;

    if (tid < 30)                  epi[tid] = g_ep[tid];
    if (tid >= 32 && tid < 82)     epi[30 + tid - 32] = W1[tid - 32];
    if (tid >= 96 && tid < 101)    epi[80 + tid - 96] = W2[tid - 96];
    if (tid == 101)                epi[85] = b2[0];
    if (tid < RPB * 10)            pre0s[tid] = g_pre0[bbase * 10 + tid];

    // 40 weight floats as 20 packed f32x2: u[kk*5+p]
    union { float4 v[10]; unsigned long long u[20]; } wr;
    {
        const float4* wp = reinterpret_cast<const float4*>(W0 + (1024 + 4 * tid) * 10);
#pragma unroll
        for (int i = 0; i < 10; ++i) wr.v[i] = wp[i];
    }

    const float* hb = h + (size_t)rowbase * 1024 + 4 * tid;
    float4 P[4];
#pragma unroll
    for (int i = 0; i < 4; ++i)
        P[i] = *reinterpret_cast<const float4*>(hb + (size_t)i * 1024);

    __syncthreads();   // smem staging visible

    float* myred = red + (warp * 8 + (lane & 7)) * 10;

#pragma unroll
    for (int it = 0; it < RPB; ++it) {
        float4 cv = P[it & 3];
        if (it < RPB - 4)
            P[it & 3] = *reinterpret_cast<const float4*>(hb + (size_t)(it + 4) * 1024);

        unsigned long long acc[5];
        unsigned long long hh;
        hh = pack2(cv.x);
#pragma unroll
        for (int p = 0; p < 5; ++p) fmul2(acc[p], hh, wr.u[p]);
        hh = pack2(cv.y);
#pragma unroll
        for (int p = 0; p < 5; ++p) ffma2(acc[p], hh, wr.u[5 + p]);
        hh = pack2(cv.z);
#pragma unroll
        for (int p = 0; p < 5; ++p) ffma2(acc[p], hh, wr.u[10 + p]);
        hh = pack2(cv.w);
#pragma unroll
        for (int p = 0; p < 5; ++p) ffma2(acc[p], hh, wr.u[15 + p]);

        float pj[10];
#pragma unroll
        for (int p = 0; p < 5; ++p) unpack2(acc[p], pj[2 * p], pj[2 * p + 1]);

#pragma unroll
        for (int j = 0; j < 10; ++j) {
            pj[j] += __shfl_xor_sync(0xffffffffu, pj[j], 16);
            pj[j] += __shfl_xor_sync(0xffffffffu, pj[j], 8);
        }
        if (lane < 8) {
            float2* rb = reinterpret_cast<float2*>(myred + it * RSTRIDE);
#pragma unroll
            for (int p = 0; p < 5; ++p) rb[p] = make_float2(pj[2 * p], pj[2 * p + 1]);
        }
    }
    __syncthreads();

    // block reduce: 160 (row,j) sums, each over 64 partials
    if (tid < RPB * 10) {
        int rl = tid / 10;
        int j  = tid - rl * 10;
        const float* base = red + rl * RSTRIDE + j;
        float s0 = 0.f, s1 = 0.f, s2 = 0.f, s3 = 0.f;
#pragma unroll
        for (int q = 0; q < 16; ++q) {
            s0 += base[(4 * q) * 10];
            s1 += base[(4 * q + 1) * 10];
            s2 += base[(4 * q + 2) * 10];
            s3 += base[(4 * q + 3) * 10];
        }
        dsum[tid] = (s0 + s1) + (s2 + s3);
    }
    __syncthreads();

    // fused MLP epilogue (16 rows) + warp-0 online softmax stats
    if (tid < 32) {
        float sc = -1e30f;
        if (tid < RPB) {
            int row = rowbase + tid;
            float x0[10];
#pragma unroll
            for (int j = 0; j < 10; ++j) {
                float d = dsum[tid * 10 + j] + pre0s[tid * 10 + j];
                x0[j] = fmaxf(fmaf(d, epi[j], epi[10 + j]), 0.f);
            }
            sc = epi[85];
#pragma unroll
            for (int i = 0; i < 5; ++i) {
                float z = 0.f;
#pragma unroll
                for (int j = 0; j < 10; ++j)
                    z = fmaf(x0[j], epi[30 + j * 5 + i], z);
                float x1 = fmaxf(fmaf(z, epi[20 + i], epi[25 + i]), 0.f);
                sc = fmaf(x1, epi[80 + i], sc);
            }
            if (row < T_DIM) g_scores[row] = sc;
        }
        float m = sc;
#pragma unroll
        for (int o = 16; o > 0; o >>= 1)
            m = fmaxf(m, __shfl_xor_sync(0xffffffffu, m, o));
        float e = (tid < RPB) ? expf(sc - m) : 0.f;
#pragma unroll
        for (int o = 16; o > 0; o >>= 1)
            e += __shfl_xor_sync(0xffffffffu, e, o);
        if (tid == 0) {
            g_bmax[blockIdx.x] = m;
            g_bsum[blockIdx.x] = e;
        }
    }
}

// ---------------------------------------------------------------------------
// K2: combine 2048 (max, expsum) pairs -> M, S; write 512 weights.
// ---------------------------------------------------------------------------
__global__ void combine_kernel()
{
    __shared__ float sm[512];
    __shared__ float MS[2];
    int tid = threadIdx.x;

    float lm = -1e30f;
    float bm[4];
#pragma unroll
    for (int i = 0; i < 4; ++i) {
        bm[i] = g_bmax[tid * 4 + i];
        lm = fmaxf(lm, bm[i]);
    }
    sm[tid] = lm;
    __syncthreads();
    for (int s = 256; s > 0; s >>= 1) {
        if (tid < s) sm[tid] = fmaxf(sm[tid], sm[tid + s]);
        __syncthreads();
    }
    if (tid == 0) MS[0] = sm[0];
    __syncthreads();
    float M = MS[0];

    float ls = 0.f;
#pragma unroll
    for (int i = 0; i < 4; ++i)
        ls += g_bsum[tid * 4 + i] * expf(bm[i] - M);
    sm[tid] = ls;
    __syncthreads();
    for (int s = 256; s > 0; s >>= 1) {
        if (tid < s) sm[tid] += sm[tid + s];
        __syncthreads();
    }
    if (tid == 0) MS[1] = 1.0f / sm[0];
    __syncthreads();

    g_w[tid] = expf(g_scores[tid] - M) * MS[1];
}

// ---------------------------------------------------------------------------
// K3: ci[b,:] = sum_tau w[tau] * h[tau,b,:]
// grid (8 chunks of 128 cols, 64 b) x 512 threads. Each warp runs FOUR
// independent t-streams (t = i*64 + w + {0,16,32,48}) -> 4x MLP per thread.
// ---------------------------------------------------------------------------
__global__ __launch_bounds__(512)
void wsum_kernel(const float* __restrict__ h, float* __restrict__ out)
{
    __shared__ float ws[T_DIM];
    __shared__ float part[16][128];

    int tid  = threadIdx.x;
    int w    = tid >> 5;
    int lane = tid & 31;
    int c = blockIdx.x;           // 128-col chunk
    int b = blockIdx.y;

    if (tid < 128)
        reinterpret_cast<float4*>(ws)[tid] = reinterpret_cast<const float4*>(g_w)[tid];
    __syncthreads();

    const float* hp = h + (size_t)b * 1024 + c * 128 + 4 * lane;
    float4 a0 = make_float4(0.f, 0.f, 0.f, 0.f);
    float4 a1 = make_float4(0.f, 0.f, 0.f, 0.f);
    float4 a2 = make_float4(0.f, 0.f, 0.f, 0.f);
    float4 a3 = make_float4(0.f, 0.f, 0.f, 0.f);
#pragma unroll 2
    for (int i = 0; i < T_DIM / 64; ++i) {
        int t0 = i * 64 + w;
        float4 h0 = *reinterpret_cast<const float4*>(hp + (size_t)t0 * (B_DIM * HU));
        float4 h1 = *reinterpret_cast<const float4*>(hp + (size_t)(t0 + 16) * (B_DIM * HU));
        float4 h2 = *reinterpret_cast<const float4*>(hp + (size_t)(t0 + 32) * (B_DIM * HU));
        float4 h3 = *reinterpret_cast<const float4*>(hp + (size_t)(t0 + 48) * (B_DIM * HU));
        float w0 = ws[t0];
        float w1 = ws[t0 + 16];
        float w2 = ws[t0 + 32];
        float w3 = ws[t0 + 48];
        a0.x = fmaf(w0, h0.x, a0.x); a0.y = fmaf(w0, h0.y, a0.y);
        a0.z = fmaf(w0, h0.z, a0.z); a0.w = fmaf(w0, h0.w, a0.w);
        a1.x = fmaf(w1, h1.x, a1.x); a1.y = fmaf(w1, h1.y, a1.y);
        a1.z = fmaf(w1, h1.z, a1.z); a1.w = fmaf(w1, h1.w, a1.w);
        a2.x = fmaf(w2, h2.x, a2.x); a2.y = fmaf(w2, h2.y, a2.y);
        a2.z = fmaf(w2, h2.z, a2.z); a2.w = fmaf(w2, h2.w, a2.w);
        a3.x = fmaf(w3, h3.x, a3.x); a3.y = fmaf(w3, h3.y, a3.y);
        a3.z = fmaf(w3, h3.z, a3.z); a3.w = fmaf(w3, h3.w, a3.w);
    }
    a0.x = (a0.x + a1.x) + (a2.x + a3.x);
    a0.y = (a0.y + a1.y) + (a2.y + a3.y);
    a0.z = (a0.z + a1.z) + (a2.z + a3.z);
    a0.w = (a0.w + a1.w) + (a2.w + a3.w);
    *reinterpret_cast<float4*>(&part[w][4 * lane]) = a0;
    __syncthreads();

    if (tid < 128) {
        float s0 = part[0][tid], s1 = part[1][tid];
        float s2 = part[2][tid], s3 = part[3][tid];
#pragma unroll
        for (int q = 4; q < 16; q += 4) {
            s0 += part[q][tid];
            s1 += part[q + 1][tid];
            s2 += part[q + 2][tid];
            s3 += part[q + 3][tid];
        }
        out[b * 1024 + c * 128 + tid] = (s0 + s1) + (s2 + s3);
    }
}

// ---------------------------------------------------------------------------
extern "C" void kernel_launch(void* const* d_in, const int* in_sizes, int n_in,
                              void* d_out, int out_size)
{
    const float* si  = (const float*)d_in[0];
    const float* h   = (const float*)d_in[1];
    const float* W0  = (const float*)d_in[2];
    const float* b0  = (const float*)d_in[3];
    const float* g0  = (const float*)d_in[4];
    const float* be0 = (const float*)d_in[5];
    const float* m0  = (const float*)d_in[6];
    const float* v0  = (const float*)d_in[7];
    const float* W1  = (const float*)d_in[8];
    const float* b1  = (const float*)d_in[9];
    const float* g1  = (const float*)d_in[10];
    const float* be1 = (const float*)d_in[11];
    const float* m1  = (const float*)d_in[12];
    const float* v1  = (const float*)d_in[13];
    const float* W2  = (const float*)d_in[14];
    const float* b2  = (const float*)d_in[15];
    float* out = (float*)d_out;

    prep_kernel<<<B_DIM, 256>>>(si, W0, b0, g0, be0, m0, v0, b1, g1, be1, m1, v1);
    score_kernel<<<NBLK, 256>>>(h, W0, W1, W2, b2);
    combine_kernel<<<1, 512>>>();
    wsum_kernel<<<dim3(8, B_DIM), 512>>>(h, out);
}

// round 7
// speedup vs baseline: 1.4046x; 1.0528x over previous
#include <cuda_runtime.h>
#include <cuda_bf16.h>
#include <math.h>

// ----------------------------------------------------------------------------
// Attention_13314398617962   (t=512, b=64, s=1024, hu=1024)
//   scores[t,b] = MLP(concat(si[b], h[t,b]))   (2048 -> 10 -> 5 -> 1, BN+relu)
//   a = softmax(scores.flatten())              (over all 32768)
//   ci[b,:] = sum_tau a[tau] * h[tau_t, tau_b, :]   (tau < 512)
// ----------------------------------------------------------------------------

#define T_DIM 512
#define B_DIM 64
#define HU 1024
#define NROWS (T_DIM * B_DIM)   // 32768
#define RPB 16                  // rows per block in score kernel
#define NBLK (NROWS / RPB)      // 2048
#define RSTRIDE 336             // padded floats per row-slot in red[] (32 partials x 10)

__device__ float g_pre0[B_DIM * 10];   // si @ W0[:1024] per b (raw dot)
__device__ float g_ep[30];             // s0[10] t0[10] s1[5] t1[5]
__device__ float g_scores[T_DIM];      // raw scores for rows < 512
__device__ float g_w[T_DIM];           // softmax weights
__device__ float g_bmax[NBLK];
__device__ float g_bsum[NBLK];

// ---------------------------------------------------------------------------
__device__ __forceinline__ void ffma2(unsigned long long& d,
                                      unsigned long long a,
                                      unsigned long long b)
{
    asm("fma.rn.f32x2 %0, %1, %2, %0;" : "+l"(d) : "l"(a), "l"(b));
}
__device__ __forceinline__ void fmul2(unsigned long long& d,
                                      unsigned long long a,
                                      unsigned long long b)
{
    asm("mul.rn.f32x2 %0, %1, %2;" : "=l"(d) : "l"(a), "l"(b));
}
__device__ __forceinline__ unsigned long long pack2(float x)
{
    unsigned long long r;
    asm("mov.b64 %0, {%1, %1};" : "=l"(r) : "f"(x));
    return r;
}
__device__ __forceinline__ void unpack2(unsigned long long v, float& lo, float& hi)
{
    asm("mov.b64 {%0, %1}, %2;" : "=f"(lo), "=f"(hi) : "l"(v));
}

// ---------------------------------------------------------------------------
// K0: per-b si contribution (coalesced W0 reads) + folded BN constants.
// ---------------------------------------------------------------------------
__global__ __launch_bounds__(256)
void prep_kernel(const float* __restrict__ si,
                 const float* __restrict__ W0,
                 const float* __restrict__ b0,
                 const float* __restrict__ g0,
                 const float* __restrict__ be0,
                 const float* __restrict__ m0,
                 const float* __restrict__ v0,
                 const float* __restrict__ b1,
                 const float* __restrict__ g1,
                 const float* __restrict__ be1,
                 const float* __restrict__ m1,
                 const float* __restrict__ v1)
{
    __shared__ float red[64][10];

    int b = blockIdx.x;
    int tid = threadIdx.x;
    int lane = tid & 31;
    int warp = tid >> 5;

    float wv[40];
    {
        const float4* wp = reinterpret_cast<const float4*>(W0 + 4 * tid * 10);
#pragma unroll
        for (int i = 0; i < 10; ++i)
            reinterpret_cast<float4*>(wv)[i] = wp[i];
    }
    float4 sv = reinterpret_cast<const float4*>(si + b * 1024)[tid];

    float pj[10];
#pragma unroll
    for (int j = 0; j < 10; ++j) {
        float a = sv.x * wv[j];
        a = fmaf(sv.y, wv[10 + j], a);
        a = fmaf(sv.z, wv[20 + j], a);
        a = fmaf(sv.w, wv[30 + j], a);
        pj[j] = a;
    }
#pragma unroll
    for (int j = 0; j < 10; ++j) {
        pj[j] += __shfl_xor_sync(0xffffffffu, pj[j], 16);
        pj[j] += __shfl_xor_sync(0xffffffffu, pj[j], 8);
    }
    if (lane < 8) {
#pragma unroll
        for (int j = 0; j < 10; ++j) red[warp * 8 + lane][j] = pj[j];
    }
    __syncthreads();

    if (tid < 10) {
        float s = 0.f;
#pragma unroll
        for (int q = 0; q < 64; ++q) s += red[q][tid];
        g_pre0[b * 10 + tid] = s;
    }

    if (b == 0) {
        if (tid >= 32 && tid < 42) {
            int i = tid - 32;
            float s = g0[i] * (1.0f / sqrtf(v0[i] + 1e-5f));
            g_ep[i] = s;
            g_ep[10 + i] = (b0[i] - m0[i]) * s + be0[i];
        } else if (tid >= 64 && tid < 69) {
            int i = tid - 64;
            float s = g1[i] * (1.0f / sqrtf(v1[i] + 1e-5f));
            g_ep[20 + i] = s;
            g_ep[25 + i] = (b1[i] - m1[i]) * s + be1[i];
        }
    }
}

// ---------------------------------------------------------------------------
// K1: scores + per-block online softmax stats. 16 rows/block, 2048 blocks.
// 256 threads cover ONE row per iteration; thread owns k = 4*tid..4*tid+3
// (40 weight floats as 20 packed f32x2). THREE shfl rounds -> 4 partials per
// warp -> red[] is only 21 KB, enabling 3 CTAs/SM (24 warps, 36 KB loads in
// flight). 3-deep prefetch ring. __launch_bounds__(256,3) -> <=85 regs.
// ---------------------------------------------------------------------------
__global__ __launch_bounds__(256, 3)
void score_kernel(const float* __restrict__ h,
                  const float* __restrict__ W0,
                  const float* __restrict__ W1,
                  const float* __restrict__ W2,
                  const float* __restrict__ b2)
{
    __shared__ float red[RPB * RSTRIDE];      // [row][part*10 + j]  21.5 KB
    __shared__ float pre0s[RPB * 10];
    __shared__ float dsum[RPB * 10];
    __shared__ float epi[86];                 // s0 t0 s1 t1 W1[50] W2[5] b2

    int tid  = threadIdx.x;
    int lane = tid & 31;
    int warp = tid >> 5;
    int rowbase = blockIdx.x * RPB;
    int bbase   = rowbase & 63;

    if (tid < 30)                  epi[tid] = g_ep[tid];
    if (tid >= 32 && tid < 82)     epi[30 + tid - 32] = W1[tid - 32];
    if (tid >= 96 && tid < 101)    epi[80 + tid - 96] = W2[tid - 96];
    if (tid == 101)                epi[85] = b2[0];
    if (tid < RPB * 10)            pre0s[tid] = g_pre0[bbase * 10 + tid];

    // 40 weight floats as 20 packed f32x2: u[kk*5+p]
    union { float4 v[10]; unsigned long long u[20]; } wr;
    {
        const float4* wp = reinterpret_cast<const float4*>(W0 + (1024 + 4 * tid) * 10);
#pragma unroll
        for (int i = 0; i < 10; ++i) wr.v[i] = wp[i];
    }

    const float* hb = h + (size_t)rowbase * 1024 + 4 * tid;
    float4 P0 = *reinterpret_cast<const float4*>(hb);
    float4 P1 = *reinterpret_cast<const float4*>(hb + 1024);
    float4 P2 = *reinterpret_cast<const float4*>(hb + 2048);

    __syncthreads();   // smem staging visible

    float* myred = red + (warp * 4 + (lane & 3)) * 10;

#pragma unroll 4
    for (int it = 0; it < RPB; ++it) {
        float4 cv = P0;
        P0 = P1; P1 = P2;
        if (it < RPB - 3)
            P2 = *reinterpret_cast<const float4*>(hb + (size_t)(it + 3) * 1024);

        unsigned long long acc[5];
        unsigned long long hh;
        hh = pack2(cv.x);
#pragma unroll
        for (int p = 0; p < 5; ++p) fmul2(acc[p], hh, wr.u[p]);
        hh = pack2(cv.y);
#pragma unroll
        for (int p = 0; p < 5; ++p) ffma2(acc[p], hh, wr.u[5 + p]);
        hh = pack2(cv.z);
#pragma unroll
        for (int p = 0; p < 5; ++p) ffma2(acc[p], hh, wr.u[10 + p]);
        hh = pack2(cv.w);
#pragma unroll
        for (int p = 0; p < 5; ++p) ffma2(acc[p], hh, wr.u[15 + p]);

        float pj[10];
#pragma unroll
        for (int p = 0; p < 5; ++p) unpack2(acc[p], pj[2 * p], pj[2 * p + 1]);

#pragma unroll
        for (int j = 0; j < 10; ++j) {
            pj[j] += __shfl_xor_sync(0xffffffffu, pj[j], 16);
            pj[j] += __shfl_xor_sync(0xffffffffu, pj[j], 8);
            pj[j] += __shfl_xor_sync(0xffffffffu, pj[j], 4);
        }
        if (lane < 4) {
            float2* rb = reinterpret_cast<float2*>(myred + it * RSTRIDE);
#pragma unroll
            for (int p = 0; p < 5; ++p) rb[p] = make_float2(pj[2 * p], pj[2 * p + 1]);
        }
    }
    __syncthreads();

    // block reduce: 160 (row,j) sums, each over 32 partials (stride 10 floats)
    if (tid < RPB * 10) {
        int rl = tid / 10;
        int j  = tid - rl * 10;
        const float* base = red + rl * RSTRIDE + j;
        float s0 = 0.f, s1 = 0.f, s2 = 0.f, s3 = 0.f;
#pragma unroll
        for (int q = 0; q < 8; ++q) {
            s0 += base[(4 * q) * 10];
            s1 += base[(4 * q + 1) * 10];
            s2 += base[(4 * q + 2) * 10];
            s3 += base[(4 * q + 3) * 10];
        }
        dsum[tid] = (s0 + s1) + (s2 + s3);
    }
    __syncthreads();

    // fused MLP epilogue (16 rows) + warp-0 online softmax stats
    if (tid < 32) {
        float sc = -1e30f;
        if (tid < RPB) {
            int row = rowbase + tid;
            float x0[10];
#pragma unroll
            for (int j = 0; j < 10; ++j) {
                float d = dsum[tid * 10 + j] + pre0s[tid * 10 + j];
                x0[j] = fmaxf(fmaf(d, epi[j], epi[10 + j]), 0.f);
            }
            sc = epi[85];
#pragma unroll
            for (int i = 0; i < 5; ++i) {
                float z = 0.f;
#pragma unroll
                for (int j = 0; j < 10; ++j)
                    z = fmaf(x0[j], epi[30 + j * 5 + i], z);
                float x1 = fmaxf(fmaf(z, epi[20 + i], epi[25 + i]), 0.f);
                sc = fmaf(x1, epi[80 + i], sc);
            }
            if (row < T_DIM) g_scores[row] = sc;
        }
        float m = sc;
#pragma unroll
        for (int o = 16; o > 0; o >>= 1)
            m = fmaxf(m, __shfl_xor_sync(0xffffffffu, m, o));
        float e = (tid < RPB) ? expf(sc - m) : 0.f;
#pragma unroll
        for (int o = 16; o > 0; o >>= 1)
            e += __shfl_xor_sync(0xffffffffu, e, o);
        if (tid == 0) {
            g_bmax[blockIdx.x] = m;
            g_bsum[blockIdx.x] = e;
        }
    }
}

// ---------------------------------------------------------------------------
// K2: combine 2048 (max, expsum) pairs -> M, S; write 512 weights.
// ---------------------------------------------------------------------------
__global__ void combine_kernel()
{
    __shared__ float sm[512];
    __shared__ float MS[2];
    int tid = threadIdx.x;

    float lm = -1e30f;
    float bm[4];
#pragma unroll
    for (int i = 0; i < 4; ++i) {
        bm[i] = g_bmax[tid * 4 + i];
        lm = fmaxf(lm, bm[i]);
    }
    sm[tid] = lm;
    __syncthreads();
    for (int s = 256; s > 0; s >>= 1) {
        if (tid < s) sm[tid] = fmaxf(sm[tid], sm[tid + s]);
        __syncthreads();
    }
    if (tid == 0) MS[0] = sm[0];
    __syncthreads();
    float M = MS[0];

    float ls = 0.f;
#pragma unroll
    for (int i = 0; i < 4; ++i)
        ls += g_bsum[tid * 4 + i] * expf(bm[i] - M);
    sm[tid] = ls;
    __syncthreads();
    for (int s = 256; s > 0; s >>= 1) {
        if (tid < s) sm[tid] += sm[tid + s];
        __syncthreads();
    }
    if (tid == 0) MS[1] = 1.0f / sm[0];
    __syncthreads();

    g_w[tid] = expf(g_scores[tid] - M) * MS[1];
}

// ---------------------------------------------------------------------------
// K3: ci[b,:] = sum_tau w[tau] * h[tau,b,:]
// grid (8 chunks of 128 cols, 64 b) x 512 threads (16 warps, t == w mod 16).
// (R4 configuration: best measured, 24.35 us)
// ---------------------------------------------------------------------------
__global__ __launch_bounds__(512)
void wsum_kernel(const float* __restrict__ h, float* __restrict__ out)
{
    __shared__ float ws[T_DIM];
    __shared__ float part[16][128];

    int tid  = threadIdx.x;
    int w    = tid >> 5;
    int lane = tid & 31;
    int c = blockIdx.x;           // 128-col chunk
    int b = blockIdx.y;

    if (tid < 128)
        reinterpret_cast<float4*>(ws)[tid] = reinterpret_cast<const float4*>(g_w)[tid];
    __syncthreads();

    const float* hp = h + (size_t)b * 1024 + c * 128 + 4 * lane;
    float4 acc = make_float4(0.f, 0.f, 0.f, 0.f);
#pragma unroll 8
    for (int i = 0; i < T_DIM / 16; ++i) {
        int t = i * 16 + w;
        float4 hv = *reinterpret_cast<const float4*>(hp + (size_t)t * (B_DIM * HU));
        float wv = ws[t];
        acc.x = fmaf(wv, hv.x, acc.x);
        acc.y = fmaf(wv, hv.y, acc.y);
        acc.z = fmaf(wv, hv.z, acc.z);
        acc.w = fmaf(wv, hv.w, acc.w);
    }
    *reinterpret_cast<float4*>(&part[w][4 * lane]) = acc;
    __syncthreads();

    if (tid < 128) {
        float s0 = part[0][tid], s1 = part[1][tid];
        float s2 = part[2][tid], s3 = part[3][tid];
#pragma unroll
        for (int q = 4; q < 16; q += 4) {
            s0 += part[q][tid];
            s1 += part[q + 1][tid];
            s2 += part[q + 2][tid];
            s3 += part[q + 3][tid];
        }
        out[b * 1024 + c * 128 + tid] = (s0 + s1) + (s2 + s3);
    }
}

// ---------------------------------------------------------------------------
extern "C" void kernel_launch(void* const* d_in, const int* in_sizes, int n_in,
                              void* d_out, int out_size)
{
    const float* si  = (const float*)d_in[0];
    const float* h   = (const float*)d_in[1];
    const float* W0  = (const float*)d_in[2];
    const float* b0  = (const float*)d_in[3];
    const float* g0  = (const float*)d_in[4];
    const float* be0 = (const float*)d_in[5];
    const float* m0  = (const float*)d_in[6];
    const float* v0  = (const float*)d_in[7];
    const float* W1  = (const float*)d_in[8];
    const float* b1  = (const float*)d_in[9];
    const float* g1  = (const float*)d_in[10];
    const float* be1 = (const float*)d_in[11];
    const float* m1  = (const float*)d_in[12];
    const float* v1  = (const float*)d_in[13];
    const float* W2  = (const float*)d_in[14];
    const float* b2  = (const float*)d_in[15];
    float* out = (float*)d_out;

    prep_kernel<<<B_DIM, 256>>>(si, W0, b0, g0, be0, m0, v0, b1, g1, be1, m1, v1);
    score_kernel<<<NBLK, 256>>>(h, W0, W1, W2, b2);
    combine_kernel<<<1, 512>>>();
    wsum_kernel<<<dim3(8, B_DIM), 512>>>(h, out);
}